// round 6
// baseline (speedup 1.0000x reference)
#include <cuda_runtime.h>
#include <cstdint>

// DCT per 8x8 patch == out(N,64) = X(N,64) @ (C ⊗ C), separable two-pass.
// Fast 8-point DCT (even/odd butterfly): 36 ops/row, 576/strip (was 1024).
// cp.async double-buffered CTA-wide pipeline (R4 skeleton), streaming stores.

#define THREADS     128
#define TILE_STRIPS 128
#define TILE_F4     (TILE_STRIPS * 16)   // float4 per tile in gmem
#define PAD_F4      (TILE_STRIPS * 17)   // padded float4 per tile in smem
#define NBUF        2

__device__ __forceinline__ void cp_async16(float4* smem_dst, const float4* gsrc)
{
    uint32_t s = (uint32_t)__cvta_generic_to_shared(smem_dst);
    asm volatile("cp.async.cg.shared.global [%0], [%1], 16;\n" :: "r"(s), "l"(gsrc));
}
__device__ __forceinline__ void cp_commit()  { asm volatile("cp.async.commit_group;\n" ::: "memory"); }
__device__ __forceinline__ void cp_wait1()   { asm volatile("cp.async.wait_group 1;\n" ::: "memory"); }

// out[j] = sum_v a[v] * CT[v][j],  CT[v][j] = s(v) cos((2j+1) v pi/16).
// Even/odd split over v: ev_j (v=0,2,4,6) folded, od_j (v=1,3,5,7) direct.
// out[j] = ev_j + od_j, out[7-j] = ev_j - od_j  (j=0..3).
__device__ __forceinline__ void dct8_fast(const float a[8], float o[8])
{
    const float c4 = 0.353553391f;           // s(0)=s(4) magnitude
    const float c2a = 0.461939766f, c2b = 0.191341716f;   // CT[2][0], CT[2][1]

    float s04 = (a[0] + a[4]) * c4;          // A
    float d04 = (a[0] - a[4]) * c4;          // B
    float P = fmaf(a[6], c2b,  a[2] * c2a);  // .4619*x2 + .1913*x6
    float Q = fmaf(a[6], -c2a, a[2] * c2b);  // .1913*x2 - .4619*x6

    float ev0 = s04 + P, ev1 = d04 + Q, ev2 = d04 - Q, ev3 = s04 - P;

    // odd coefficients CT[1][j], CT[3][j], CT[5][j], CT[7][j] for j=0..3
    const float k1 = 0.490392640f, k3 = 0.415734806f,
                k5 = 0.277785117f, k7 = 0.097545161f;
    float od0 = fmaf(a[1],  k1, fmaf(a[3],  k3, fmaf(a[5],  k5, a[7] *  k7)));
    float od1 = fmaf(a[1],  k3, fmaf(a[3], -k7, fmaf(a[5], -k1, a[7] * -k5)));
    float od2 = fmaf(a[1],  k5, fmaf(a[3], -k1, fmaf(a[5],  k7, a[7] *  k3)));
    float od3 = fmaf(a[1],  k7, fmaf(a[3], -k5, fmaf(a[5],  k3, a[7] * -k1)));

    o[0] = ev0 + od0;  o[7] = ev0 - od0;
    o[1] = ev1 + od1;  o[6] = ev1 - od1;
    o[2] = ev2 + od2;  o[5] = ev2 - od2;
    o[3] = ev3 + od3;  o[4] = ev3 - od3;
}

// Full 64-point separable transform on one strip held in x[64] (in place).
__device__ __forceinline__ void dct64_fast(float x[64])
{
    // Stage 1: rows (contiguous 8): x[u*8+j] <- sum_v x[u*8+v] CT[v][j]
#pragma unroll
    for (int u = 0; u < 8; ++u) {
        float a[8], o[8];
#pragma unroll
        for (int v = 0; v < 8; ++v) a[v] = x[u * 8 + v];
        dct8_fast(a, o);
#pragma unroll
        for (int j = 0; j < 8; ++j) x[u * 8 + j] = o[j];
    }
    // Stage 2: columns: x[i*8+j] <- sum_u x[u*8+j] CT[u][i]
#pragma unroll
    for (int j = 0; j < 8; ++j) {
        float a[8], o[8];
#pragma unroll
        for (int u = 0; u < 8; ++u) a[u] = x[u * 8 + j];
        dct8_fast(a, o);
#pragma unroll
        for (int i = 0; i < 8; ++i) x[i * 8 + j] = o[i];
    }
}

__global__ __launch_bounds__(THREADS)
void dct_pipe_kernel(const float4* __restrict__ in4, float4* __restrict__ out4,
                     int ntiles)
{
    __shared__ float4 sm[NBUF * PAD_F4];
    const int t    = threadIdx.x;
    const int trow = t >> 4;
    const int tcol = t & 15;
    const int pad_off = trow * 17 + tcol;

    const int stride = gridDim.x;
    int tile = blockIdx.x;

    if (tile < ntiles) {
        const float4* g = in4 + (size_t)tile * TILE_F4;
#pragma unroll
        for (int k = 0; k < 16; ++k)
            cp_async16(&sm[(k * 8) * 17 + pad_off], &g[k * THREADS + t]);
    }
    cp_commit();

    int buf = 0;
    for (int i = tile; i < ntiles; i += stride) {
        int nxt = i + stride;
        if (nxt < ntiles) {
            const float4* g = in4 + (size_t)nxt * TILE_F4;
            float4* d = &sm[(buf ^ 1) * PAD_F4];
#pragma unroll
            for (int k = 0; k < 16; ++k)
                cp_async16(&d[(k * 8) * 17 + pad_off], &g[k * THREADS + t]);
        }
        cp_commit();
        cp_wait1();
        __syncthreads();

        float4* s  = &sm[buf * PAD_F4];
        float4* sp = s + t * 17;

        float x[64];
#pragma unroll
        for (int k = 0; k < 16; ++k) {
            float4 v = sp[k];
            x[4 * k + 0] = v.x; x[4 * k + 1] = v.y;
            x[4 * k + 2] = v.z; x[4 * k + 3] = v.w;
        }

        dct64_fast(x);

#pragma unroll
        for (int k = 0; k < 16; ++k)
            sp[k] = make_float4(x[4 * k + 0], x[4 * k + 1], x[4 * k + 2], x[4 * k + 3]);
        __syncthreads();

        // Coalesced smem -> gmem, streaming (evict-first: keep input L2-resident).
        float4* go = out4 + (size_t)i * TILE_F4;
#pragma unroll
        for (int k = 0; k < 16; ++k)
            __stcs(&go[k * THREADS + t], s[(k * 8) * 17 + pad_off]);
        __syncthreads();   // buffer free before it becomes a prefetch target

        buf ^= 1;
    }
}

// Tail (strip count not divisible by 128): direct per-thread path, tiny.
__global__ void dct_tail_kernel(const float4* __restrict__ in4,
                                float4* __restrict__ out4,
                                int first_strip, int nstrips)
{
    int strip = first_strip + blockIdx.x * blockDim.x + threadIdx.x;
    if (strip >= nstrips) return;
    float x[64];
    const float4* ip = in4 + (size_t)strip * 16;
#pragma unroll
    for (int k = 0; k < 16; ++k) {
        float4 v = ip[k];
        x[4 * k + 0] = v.x; x[4 * k + 1] = v.y;
        x[4 * k + 2] = v.z; x[4 * k + 3] = v.w;
    }
    dct64_fast(x);
    float4* op = out4 + (size_t)strip * 16;
#pragma unroll
    for (int k = 0; k < 16; ++k)
        op[k] = make_float4(x[4 * k + 0], x[4 * k + 1], x[4 * k + 2], x[4 * k + 3]);
}

extern "C" void kernel_launch(void* const* d_in, const int* in_sizes, int n_in,
                              void* d_out, int out_size)
{
    const float4* in4 = (const float4*)d_in[0];  // (8,3,1024,1024) fp32 contiguous
    float4* out4      = (float4*)d_out;

    int nstrips = in_sizes[0] / 64;              // 393216 on bench shape
    int ntiles  = nstrips / TILE_STRIPS;

    if (ntiles > 0) {
        int nsm = 148;
        cudaDeviceGetAttribute(&nsm, cudaDevAttrMultiProcessorCount, 0);
        int grid = 3 * nsm;                      // exactly resident: 3 CTAs/SM by smem
        if (grid > ntiles) grid = ntiles;
        dct_pipe_kernel<<<grid, THREADS>>>(in4, out4, ntiles);
    }
    int rem = nstrips - ntiles * TILE_STRIPS;
    if (rem > 0)
        dct_tail_kernel<<<(rem + 127) / 128, 128>>>(in4, out4,
                                                    ntiles * TILE_STRIPS, nstrips);
}

// round 7
// speedup vs baseline: 1.3342x; 1.3342x over previous
#include <cuda_runtime.h>
#include <cstdint>

// DCT per 8x8 patch == out(N,64) = X(N,64) @ (C ⊗ C), separable two-pass,
// 1024 FFMA-imm per strip (rt=1 form — faster in issue slots than the 576-op
// butterfly, measured R6). One tile (128 strips) per CTA, single smem buffer:
// 34.8KB -> ~5-6 CTAs/SM; overlap across tiles comes from CTA-level phase
// desync instead of a persistent software pipeline (measured better, R4 vs R2).

#define THREADS     128
#define TILE_STRIPS 128
#define TILE_F4     (TILE_STRIPS * 16)   // float4 per tile in gmem
#define PAD_F4      (TILE_STRIPS * 17)   // padded float4 per tile in smem

#define DCT_TABLE(CT)                                                                  \
    const float CT[8][8] = {                                                           \
        {0.353553391f, 0.353553391f, 0.353553391f, 0.353553391f,                       \
         0.353553391f, 0.353553391f, 0.353553391f, 0.353553391f},                      \
        {0.490392640f, 0.415734806f, 0.277785117f, 0.097545161f,                       \
         -0.097545161f, -0.277785117f, -0.415734806f, -0.490392640f},                  \
        {0.461939766f, 0.191341716f, -0.191341716f, -0.461939766f,                     \
         -0.461939766f, -0.191341716f, 0.191341716f, 0.461939766f},                    \
        {0.415734806f, -0.097545161f, -0.490392640f, -0.277785117f,                    \
         0.277785117f, 0.490392640f, 0.097545161f, -0.415734806f},                     \
        {0.353553391f, -0.353553391f, -0.353553391f, 0.353553391f,                     \
         0.353553391f, -0.353553391f, -0.353553391f, 0.353553391f},                    \
        {0.277785117f, -0.490392640f, 0.097545161f, 0.415734806f,                      \
         -0.415734806f, -0.097545161f, 0.490392640f, -0.277785117f},                   \
        {0.191341716f, -0.461939766f, 0.461939766f, -0.191341716f,                     \
         -0.191341716f, 0.461939766f, -0.461939766f, 0.191341716f},                    \
        {0.097545161f, -0.277785117f, 0.415734806f, -0.490392640f,                     \
         0.490392640f, -0.415734806f, 0.277785117f, -0.097545161f}};

__device__ __forceinline__ void cp_async16(float4* smem_dst, const float4* gsrc)
{
    uint32_t s = (uint32_t)__cvta_generic_to_shared(smem_dst);
    asm volatile("cp.async.cg.shared.global [%0], [%1], 16;\n" :: "r"(s), "l"(gsrc));
}
__device__ __forceinline__ void cp_commit() { asm volatile("cp.async.commit_group;\n" ::: "memory"); }
__device__ __forceinline__ void cp_wait0()  { asm volatile("cp.async.wait_group 0;\n" ::: "memory"); }

__global__ __launch_bounds__(THREADS)
void dct_oneshot_kernel(const float4* __restrict__ in4, float4* __restrict__ out4)
{
    __shared__ float4 sm[PAD_F4];
    const int t    = threadIdx.x;
    const int trow = t >> 4;
    const int tcol = t & 15;
    const int pad_off = trow * 17 + tcol;

    const size_t base = (size_t)blockIdx.x * TILE_F4;

    // Coalesced gmem -> padded smem via cp.async (no register cost, 16 in flight).
#pragma unroll
    for (int k = 0; k < 16; ++k)
        cp_async16(&sm[(k * 8) * 17 + pad_off], &in4[base + k * THREADS + t]);
    cp_commit();
    cp_wait0();
    __syncthreads();

    // Own strip: smem -> regs (conflict-free via stride-17 pad).
    float x[64];
    float4* sp = sm + t * 17;
#pragma unroll
    for (int k = 0; k < 16; ++k) {
        float4 v = sp[k];
        x[4 * k + 0] = v.x; x[4 * k + 1] = v.y;
        x[4 * k + 2] = v.z; x[4 * k + 3] = v.w;
    }

    DCT_TABLE(CT);
    // Stage 1 (in place): x[u*8+j] <- sum_v x[u*8+v] * CT[v][j]
#pragma unroll
    for (int u = 0; u < 8; ++u) {
        float tr[8];
#pragma unroll
        for (int j = 0; j < 8; ++j) {
            float a = x[u * 8 + 0] * CT[0][j];
#pragma unroll
            for (int v = 1; v < 8; ++v) a = fmaf(x[u * 8 + v], CT[v][j], a);
            tr[j] = a;
        }
#pragma unroll
        for (int j = 0; j < 8; ++j) x[u * 8 + j] = tr[j];
    }
    // Stage 2: row r streamed straight back to smem (in-place buffer reuse).
#pragma unroll
    for (int r = 0; r < 8; ++r) {
        float o[8];
#pragma unroll
        for (int j = 0; j < 8; ++j) {
            float a = x[0 * 8 + j] * CT[0][r];
#pragma unroll
            for (int u = 1; u < 8; ++u) a = fmaf(x[u * 8 + j], CT[u][r], a);
            o[j] = a;
        }
        sp[2 * r + 0] = make_float4(o[0], o[1], o[2], o[3]);
        sp[2 * r + 1] = make_float4(o[4], o[5], o[6], o[7]);
    }
    __syncthreads();

    // Coalesced smem -> gmem (plain stores; __stcs measured slower, R6).
#pragma unroll
    for (int k = 0; k < 16; ++k)
        out4[base + k * THREADS + t] = sm[(k * 8) * 17 + pad_off];
}

// Tail (strip count not divisible by 128): direct per-thread path, tiny.
__global__ void dct_tail_kernel(const float4* __restrict__ in4,
                                float4* __restrict__ out4,
                                int first_strip, int nstrips)
{
    int strip = first_strip + blockIdx.x * blockDim.x + threadIdx.x;
    if (strip >= nstrips) return;
    float x[64];
    const float4* ip = in4 + (size_t)strip * 16;
#pragma unroll
    for (int k = 0; k < 16; ++k) {
        float4 v = ip[k];
        x[4 * k + 0] = v.x; x[4 * k + 1] = v.y;
        x[4 * k + 2] = v.z; x[4 * k + 3] = v.w;
    }
    DCT_TABLE(CT);
#pragma unroll
    for (int u = 0; u < 8; ++u) {
        float tr[8];
#pragma unroll
        for (int j = 0; j < 8; ++j) {
            float a = x[u * 8 + 0] * CT[0][j];
#pragma unroll
            for (int v = 1; v < 8; ++v) a = fmaf(x[u * 8 + v], CT[v][j], a);
            tr[j] = a;
        }
#pragma unroll
        for (int j = 0; j < 8; ++j) x[u * 8 + j] = tr[j];
    }
    float4* op = out4 + (size_t)strip * 16;
#pragma unroll
    for (int r = 0; r < 8; ++r) {
        float o[8];
#pragma unroll
        for (int j = 0; j < 8; ++j) {
            float a = x[0 * 8 + j] * CT[0][r];
#pragma unroll
            for (int u = 1; u < 8; ++u) a = fmaf(x[u * 8 + j], CT[u][r], a);
            o[j] = a;
        }
        op[2 * r + 0] = make_float4(o[0], o[1], o[2], o[3]);
        op[2 * r + 1] = make_float4(o[4], o[5], o[6], o[7]);
    }
}

extern "C" void kernel_launch(void* const* d_in, const int* in_sizes, int n_in,
                              void* d_out, int out_size)
{
    const float4* in4 = (const float4*)d_in[0];  // (8,3,1024,1024) fp32 contiguous
    float4* out4      = (float4*)d_out;

    int nstrips = in_sizes[0] / 64;              // 393216 on bench shape
    int ntiles  = nstrips / TILE_STRIPS;         // 3072

    if (ntiles > 0)
        dct_oneshot_kernel<<<ntiles, THREADS>>>(in4, out4);
    int rem = nstrips - ntiles * TILE_STRIPS;
    if (rem > 0)
        dct_tail_kernel<<<(rem + 127) / 128, 128>>>(in4, out4,
                                                    ntiles * TILE_STRIPS, nstrips);
}